// round 1
// baseline (speedup 1.0000x reference)
#include <cuda_runtime.h>
#include <cuda_bf16.h>
#include <cstdint>
#include <cstddef>

// ---------------------------------------------------------------------------
// Problem constants
// ---------------------------------------------------------------------------
constexpr int BATCH = 4;
constexpr int TSEQ  = 8192;
constexpr int CDIM  = 2048;
constexpr int NHEAD = 16;
constexpr int DHEAD = 128;
constexpr int NBLK  = 64;            // TSEQ / 128
constexpr int MROWS = BATCH * TSEQ;  // 32768
constexpr int N_QKV = 3 * CDIM;      // 6144

// ---------------------------------------------------------------------------
// Static scratch (no allocations allowed)
// ---------------------------------------------------------------------------
__device__ __align__(256) __nv_bfloat16 g_Xhi [(size_t)MROWS * CDIM];
__device__ __align__(256) __nv_bfloat16 g_Xlo [(size_t)MROWS * CDIM];
__device__ __align__(256) __nv_bfloat16 g_Wqh [(size_t)CDIM * N_QKV];
__device__ __align__(256) __nv_bfloat16 g_Wql [(size_t)CDIM * N_QKV];
__device__ __align__(256) __nv_bfloat16 g_Wph [(size_t)CDIM * CDIM];
__device__ __align__(256) __nv_bfloat16 g_Wpl [(size_t)CDIM * CDIM];
__device__ __align__(256) __nv_bfloat16 g_QKVh[(size_t)MROWS * N_QKV];
__device__ __align__(256) __nv_bfloat16 g_QKVl[(size_t)MROWS * N_QKV];
__device__ __align__(256) __nv_bfloat16 g_ATTh[(size_t)MROWS * CDIM];
__device__ __align__(256) __nv_bfloat16 g_ATTl[(size_t)MROWS * CDIM];

// ---------------------------------------------------------------------------
// Small device helpers
// ---------------------------------------------------------------------------
__device__ __forceinline__ uint32_t pk2(__nv_bfloat16 a, __nv_bfloat16 b) {
    __nv_bfloat162 t; t.x = a; t.y = b;
    return *reinterpret_cast<uint32_t*>(&t);
}

__device__ __forceinline__ void split2(float a, float b, uint32_t& hi, uint32_t& lo) {
    __nv_bfloat16 ha = __float2bfloat16(a);
    __nv_bfloat16 hb = __float2bfloat16(b);
    __nv_bfloat16 la = __float2bfloat16(a - __bfloat162float(ha));
    __nv_bfloat16 lb = __float2bfloat16(b - __bfloat162float(hb));
    hi = pk2(ha, hb);
    lo = pk2(la, lb);
}

__device__ __forceinline__ void cp16(void* s, const void* g) {
    uint32_t sa = (uint32_t)__cvta_generic_to_shared(s);
    asm volatile("cp.async.cg.shared.global [%0], [%1], 16;" :: "r"(sa), "l"(g));
}
__device__ __forceinline__ void cp_commit() {
    asm volatile("cp.async.commit_group;");
}
template <int N>
__device__ __forceinline__ void cp_wait() {
    asm volatile("cp.async.wait_group %0;" :: "n"(N));
}

__device__ __forceinline__ void ldsm4(uint32_t* d, const void* p) {
    uint32_t a = (uint32_t)__cvta_generic_to_shared(p);
    asm volatile("ldmatrix.sync.aligned.m8n8.x4.shared.b16 {%0,%1,%2,%3}, [%4];"
                 : "=r"(d[0]), "=r"(d[1]), "=r"(d[2]), "=r"(d[3]) : "r"(a));
}
__device__ __forceinline__ void ldsm2(uint32_t* d, const void* p) {
    uint32_t a = (uint32_t)__cvta_generic_to_shared(p);
    asm volatile("ldmatrix.sync.aligned.m8n8.x2.shared.b16 {%0,%1}, [%2];"
                 : "=r"(d[0]), "=r"(d[1]) : "r"(a));
}
__device__ __forceinline__ void ldsm2t(uint32_t* d, const void* p) {
    uint32_t a = (uint32_t)__cvta_generic_to_shared(p);
    asm volatile("ldmatrix.sync.aligned.m8n8.x2.trans.shared.b16 {%0,%1}, [%2];"
                 : "=r"(d[0]), "=r"(d[1]) : "r"(a));
}

__device__ __forceinline__ void mma16816(float* c, const uint32_t* a, const uint32_t* b) {
    asm volatile(
        "mma.sync.aligned.m16n8k16.row.col.f32.bf16.bf16.f32 "
        "{%0,%1,%2,%3}, {%4,%5,%6,%7}, {%8,%9}, {%0,%1,%2,%3};"
        : "+f"(c[0]), "+f"(c[1]), "+f"(c[2]), "+f"(c[3])
        : "r"(a[0]), "r"(a[1]), "r"(a[2]), "r"(a[3]), "r"(b[0]), "r"(b[1]));
}

// ---------------------------------------------------------------------------
// Split kernel: fp32 -> (bf16 hi, bf16 lo)
// ---------------------------------------------------------------------------
__global__ void split_kernel(const float4* __restrict__ src,
                             uint32_t* __restrict__ hi,
                             uint32_t* __restrict__ lo, int n4) {
    int i = blockIdx.x * blockDim.x + threadIdx.x;
    if (i >= n4) return;
    float4 v = src[i];
    uint32_t h0, l0, h1, l1;
    split2(v.x, v.y, h0, l0);
    split2(v.z, v.w, h1, l1);
    hi[2 * i]     = h0;
    hi[2 * i + 1] = h1;
    lo[2 * i]     = l0;
    lo[2 * i + 1] = l1;
}

// ---------------------------------------------------------------------------
// Split-bf16 GEMM: C[M,N] = (Ahi+Alo)[M,K] @ (Bhi+Blo)[K,N]
// Tiles: BM=128, BN=128, BK=32. 256 threads, 8 warps (2m x 4n), warp 64x32.
// SPLIT_OUT: write C as bf16 hi/lo; else write fp32.
// ---------------------------------------------------------------------------
__device__ __forceinline__ void gemm_load_tile(
    const __nv_bfloat16* __restrict__ Ahi, const __nv_bfloat16* __restrict__ Alo,
    const __nv_bfloat16* __restrict__ Bhi, const __nv_bfloat16* __restrict__ Blo,
    __nv_bfloat16* sA, __nv_bfloat16* sB,
    int buf, int kt, int m0, int n0, int Nn, int Kk, int tid)
{
    // A tile: [2 planes][128 rows][32 cols], 4 chunks of 16B per row per plane
#pragma unroll
    for (int i = 0; i < 4; i++) {
        int cidx  = tid + i * 256;
        int plane = cidx >> 9;
        int rem   = cidx & 511;
        int r     = rem >> 2;
        int ch    = rem & 3;
        const __nv_bfloat16* g = (plane ? Alo : Ahi) + (size_t)(m0 + r) * Kk + kt * 32 + ch * 8;
        int sw = ch ^ ((r >> 1) & 3);
        __nv_bfloat16* s = sA + ((buf * 2 + plane) * 128 + r) * 32 + sw * 8;
        cp16(s, g);
    }
    // B tile: [2 planes][32 rows][128 cols], 16 chunks per row per plane
#pragma unroll
    for (int i = 0; i < 4; i++) {
        int cidx  = tid + i * 256;
        int plane = cidx >> 9;
        int rem   = cidx & 511;
        int r     = rem >> 4;
        int ch    = rem & 15;
        const __nv_bfloat16* g = (plane ? Blo : Bhi) + (size_t)(kt * 32 + r) * Nn + n0 + ch * 8;
        int sw = ch ^ (r & 7);
        __nv_bfloat16* s = sB + ((buf * 2 + plane) * 32 + r) * 128 + sw * 8;
        cp16(s, g);
    }
}

template <bool SPLIT_OUT>
__global__ void __launch_bounds__(256, 1) gemm_split_kernel(
    const __nv_bfloat16* __restrict__ Ahi, const __nv_bfloat16* __restrict__ Alo,
    const __nv_bfloat16* __restrict__ Bhi, const __nv_bfloat16* __restrict__ Blo,
    __nv_bfloat16* __restrict__ Chi, __nv_bfloat16* __restrict__ Clo,
    float* __restrict__ Cf, int Mm, int Nn, int Kk)
{
    extern __shared__ __nv_bfloat16 smem[];
    __nv_bfloat16* sA = smem;          // 2 buf * 2 plane * 128 * 32 = 16384
    __nv_bfloat16* sB = smem + 16384;  // 2 buf * 2 plane * 32 * 128 = 16384

    const int tid  = threadIdx.x;
    const int lane = tid & 31;
    const int wid  = tid >> 5;
    const int m0   = blockIdx.y * 128;
    const int n0   = blockIdx.x * 128;
    const int wm   = (wid >> 2) * 64;
    const int wn   = (wid & 3) * 32;

    float c[4][4][4];
#pragma unroll
    for (int mt = 0; mt < 4; mt++)
#pragma unroll
        for (int nt = 0; nt < 4; nt++)
#pragma unroll
            for (int e = 0; e < 4; e++) c[mt][nt][e] = 0.f;

    const int nk = Kk / 32;
    gemm_load_tile(Ahi, Alo, Bhi, Blo, sA, sB, 0, 0, m0, n0, Nn, Kk, tid);
    cp_commit();

    for (int kt = 0; kt < nk; kt++) {
        if (kt + 1 < nk) {
            gemm_load_tile(Ahi, Alo, Bhi, Blo, sA, sB, (kt + 1) & 1, kt + 1, m0, n0, Nn, Kk, tid);
            cp_commit();
            cp_wait<1>();
        } else {
            cp_wait<0>();
        }
        __syncthreads();
        const int buf = kt & 1;

#pragma unroll
        for (int kk = 0; kk < 2; kk++) {
            uint32_t aH[4][4], aL[4][4];
#pragma unroll
            for (int mt = 0; mt < 4; mt++) {
                int r  = wm + mt * 16 + (lane & 15);
                int ch = kk * 2 + (lane >> 4);
                int sw = ch ^ ((r >> 1) & 3);
                ldsm4(aH[mt], sA + ((buf * 2 + 0) * 128 + r) * 32 + sw * 8);
                ldsm4(aL[mt], sA + ((buf * 2 + 1) * 128 + r) * 32 + sw * 8);
            }
            uint32_t bH[4][2], bL[4][2];
#pragma unroll
            for (int nt = 0; nt < 4; nt++) {
                int l16  = lane & 15;
                int krow = kk * 16 + l16;
                int ch   = (wn >> 3) + nt;
                int sw   = ch ^ (krow & 7);
                ldsm2t(bH[nt], sB + ((buf * 2 + 0) * 32 + krow) * 128 + sw * 8);
                ldsm2t(bL[nt], sB + ((buf * 2 + 1) * 32 + krow) * 128 + sw * 8);
            }
#pragma unroll
            for (int mt = 0; mt < 4; mt++)
#pragma unroll
                for (int nt = 0; nt < 4; nt++) {
                    mma16816(c[mt][nt], aH[mt], bH[nt]);
                    mma16816(c[mt][nt], aH[mt], bL[nt]);
                    mma16816(c[mt][nt], aL[mt], bH[nt]);
                }
        }
        __syncthreads();
    }

    // Epilogue
#pragma unroll
    for (int mt = 0; mt < 4; mt++) {
#pragma unroll
        for (int nt = 0; nt < 4; nt++) {
            int row = m0 + wm + mt * 16 + (lane >> 2);
            int col = n0 + wn + nt * 8 + (lane & 3) * 2;
            float v0 = c[mt][nt][0], v1 = c[mt][nt][1];
            float v2 = c[mt][nt][2], v3 = c[mt][nt][3];
            if (SPLIT_OUT) {
                uint32_t h, l;
                split2(v0, v1, h, l);
                *reinterpret_cast<uint32_t*>(Chi + (size_t)row * Nn + col) = h;
                *reinterpret_cast<uint32_t*>(Clo + (size_t)row * Nn + col) = l;
                split2(v2, v3, h, l);
                *reinterpret_cast<uint32_t*>(Chi + (size_t)(row + 8) * Nn + col) = h;
                *reinterpret_cast<uint32_t*>(Clo + (size_t)(row + 8) * Nn + col) = l;
            } else {
                float2 p0 = make_float2(v0, v1);
                float2 p1 = make_float2(v2, v3);
                *reinterpret_cast<float2*>(Cf + (size_t)row * Nn + col) = p0;
                *reinterpret_cast<float2*>(Cf + (size_t)(row + 8) * Nn + col) = p1;
            }
        }
    }
}

// ---------------------------------------------------------------------------
// Attention: one CTA per (b, blk, h). Q,K,V 128x128 (hi/lo bf16) in smem.
// 8 warps; warp w owns query rows [16w, 16w+16): full rows in one warp.
// ---------------------------------------------------------------------------
__device__ __forceinline__ void attn_load(__nv_bfloat16* dst,
                                          const __nv_bfloat16* __restrict__ ghi,
                                          const __nv_bfloat16* __restrict__ glo,
                                          size_t t0, int colb, int tid) {
#pragma unroll
    for (int i = 0; i < 16; i++) {
        int cidx  = tid + i * 256;
        int plane = cidx >> 11;
        int rem   = cidx & 2047;
        int r     = rem >> 4;
        int ch    = rem & 15;
        const __nv_bfloat16* g = (plane ? glo : ghi) + (t0 + r) * (size_t)N_QKV + colb + ch * 8;
        __nv_bfloat16* s = dst + (plane * 128 + r) * 128 + (ch ^ (r & 7)) * 8;
        cp16(s, g);
    }
}

__global__ void __launch_bounds__(256, 1) attn_kernel(
    const __nv_bfloat16* __restrict__ qkv_hi, const __nv_bfloat16* __restrict__ qkv_lo,
    __nv_bfloat16* __restrict__ att_hi, __nv_bfloat16* __restrict__ att_lo)
{
    extern __shared__ __nv_bfloat16 smem[];
    __nv_bfloat16* sQ = smem;           // [2][128][128]
    __nv_bfloat16* sK = smem + 32768;
    __nv_bfloat16* sV = smem + 65536;

    const int tid  = threadIdx.x;
    const int lane = tid & 31;
    const int wid  = tid >> 5;

    const int cta = blockIdx.x;
    const int h   = cta & 15;
    const int blk = (cta >> 4) & 63;
    const int b   = cta >> 10;
    const size_t t0 = (size_t)b * TSEQ + (size_t)blk * 128;

    attn_load(sQ, qkv_hi, qkv_lo, t0, h * DHEAD, tid);
    attn_load(sK, qkv_hi, qkv_lo, t0, CDIM + h * DHEAD, tid);
    cp_commit();
    attn_load(sV, qkv_hi, qkv_lo, t0, 2 * CDIM + h * DHEAD, tid);
    cp_commit();

    cp_wait<1>();   // Q, K ready
    __syncthreads();

    // ----- scores S = Q K^T (warp tile 16 x 128), split-bf16 -----
    float s[16][4];
#pragma unroll
    for (int nt = 0; nt < 16; nt++)
#pragma unroll
        for (int e = 0; e < 4; e++) s[nt][e] = 0.f;

    const int rw0 = wid * 16;
#pragma unroll
    for (int kk = 0; kk < 8; kk++) {
        uint32_t qH[4], qL[4];
        {
            int r  = rw0 + (lane & 15);
            int ch = kk * 2 + (lane >> 4);
            int sw = ch ^ (r & 7);
            ldsm4(qH, sQ + r * 128 + sw * 8);
            ldsm4(qL, sQ + (128 + r) * 128 + sw * 8);
        }
#pragma unroll
        for (int nt = 0; nt < 16; nt++) {
            uint32_t kH[2], kL[2];
            int l16  = lane & 15;
            int nrow = nt * 8 + (l16 & 7);
            int ch   = kk * 2 + (l16 >> 3);
            int sw   = ch ^ (nrow & 7);
            ldsm2(kH, sK + nrow * 128 + sw * 8);
            ldsm2(kL, sK + (128 + nrow) * 128 + sw * 8);
            mma16816(s[nt], qH, kH);
            mma16816(s[nt], qH, kL);
            mma16816(s[nt], qL, kH);
        }
    }

    // ----- causal softmax (rows fully inside warp quads) -----
    const float scale = 0.08838834764831845f;  // 1/sqrt(128)
    const int g  = lane >> 2;
    const int tq = lane & 3;
    const int r0 = rw0 + g;
    const int r1 = r0 + 8;

    float mx0 = -1e30f, mx1 = -1e30f;
#pragma unroll
    for (int nt = 0; nt < 16; nt++) {
        int j0 = nt * 8 + tq * 2;
        int j1 = j0 + 1;
        float v;
        v = s[nt][0] * scale; if (j0 > r0) v = -1e30f; s[nt][0] = v; mx0 = fmaxf(mx0, v);
        v = s[nt][1] * scale; if (j1 > r0) v = -1e30f; s[nt][1] = v; mx0 = fmaxf(mx0, v);
        v = s[nt][2] * scale; if (j0 > r1) v = -1e30f; s[nt][2] = v; mx1 = fmaxf(mx1, v);
        v = s[nt][3] * scale; if (j1 > r1) v = -1e30f; s[nt][3] = v; mx1 = fmaxf(mx1, v);
    }
    mx0 = fmaxf(mx0, __shfl_xor_sync(0xffffffffu, mx0, 1));
    mx0 = fmaxf(mx0, __shfl_xor_sync(0xffffffffu, mx0, 2));
    mx1 = fmaxf(mx1, __shfl_xor_sync(0xffffffffu, mx1, 1));
    mx1 = fmaxf(mx1, __shfl_xor_sync(0xffffffffu, mx1, 2));

    float sum0 = 0.f, sum1 = 0.f;
#pragma unroll
    for (int nt = 0; nt < 16; nt++) {
        s[nt][0] = __expf(s[nt][0] - mx0); sum0 += s[nt][0];
        s[nt][1] = __expf(s[nt][1] - mx0); sum0 += s[nt][1];
        s[nt][2] = __expf(s[nt][2] - mx1); sum1 += s[nt][2];
        s[nt][3] = __expf(s[nt][3] - mx1); sum1 += s[nt][3];
    }
    sum0 += __shfl_xor_sync(0xffffffffu, sum0, 1);
    sum0 += __shfl_xor_sync(0xffffffffu, sum0, 2);
    sum1 += __shfl_xor_sync(0xffffffffu, sum1, 1);
    sum1 += __shfl_xor_sync(0xffffffffu, sum1, 2);
    const float inv0 = 1.f / sum0;
    const float inv1 = 1.f / sum1;

    cp_wait<0>();   // V ready
    __syncthreads();

    // ----- O = P V (P re-split to hi/lo bf16 from register S-frags) -----
    float o[16][4];
#pragma unroll
    for (int nt = 0; nt < 16; nt++)
#pragma unroll
        for (int e = 0; e < 4; e++) o[nt][e] = 0.f;

#pragma unroll
    for (int kk = 0; kk < 8; kk++) {
        uint32_t aH[4], aL[4];
        split2(s[2 * kk][0],     s[2 * kk][1],     aH[0], aL[0]);
        split2(s[2 * kk][2],     s[2 * kk][3],     aH[1], aL[1]);
        split2(s[2 * kk + 1][0], s[2 * kk + 1][1], aH[2], aL[2]);
        split2(s[2 * kk + 1][2], s[2 * kk + 1][3], aH[3], aL[3]);
#pragma unroll
        for (int nt = 0; nt < 16; nt++) {
            uint32_t vH[2], vL[2];
            int l16  = lane & 15;
            int krow = kk * 16 + l16;
            int sw   = nt ^ (krow & 7);
            ldsm2t(vH, sV + krow * 128 + sw * 8);
            ldsm2t(vL, sV + (128 + krow) * 128 + sw * 8);
            mma16816(o[nt], aH, vH);
            mma16816(o[nt], aH, vL);
            mma16816(o[nt], aL, vH);
        }
    }

    // ----- epilogue: write attn out as split bf16 (input to proj GEMM) -----
    const size_t tok0 = t0 + r0;
    const size_t tok1 = t0 + r1;
#pragma unroll
    for (int nt = 0; nt < 16; nt++) {
        int col = h * DHEAD + nt * 8 + tq * 2;
        float v0 = o[nt][0] * inv0, v1 = o[nt][1] * inv0;
        float v2 = o[nt][2] * inv1, v3 = o[nt][3] * inv1;
        uint32_t hpk, lpk;
        split2(v0, v1, hpk, lpk);
        *reinterpret_cast<uint32_t*>(att_hi + tok0 * CDIM + col) = hpk;
        *reinterpret_cast<uint32_t*>(att_lo + tok0 * CDIM + col) = lpk;
        split2(v2, v3, hpk, lpk);
        *reinterpret_cast<uint32_t*>(att_hi + tok1 * CDIM + col) = hpk;
        *reinterpret_cast<uint32_t*>(att_lo + tok1 * CDIM + col) = lpk;
    }
}

// ---------------------------------------------------------------------------
// Host launcher
// ---------------------------------------------------------------------------
extern "C" void kernel_launch(void* const* d_in, const int* in_sizes, int n_in,
                              void* d_out, int out_size) {
    const float* x  = (const float*)d_in[0];
    const float* wq = (const float*)d_in[1];
    const float* wp = (const float*)d_in[2];
    float* out = (float*)d_out;

    void *pXh, *pXl, *pWqh, *pWql, *pWph, *pWpl, *pQh, *pQl, *pAh, *pAl;
    cudaGetSymbolAddress(&pXh,  g_Xhi);
    cudaGetSymbolAddress(&pXl,  g_Xlo);
    cudaGetSymbolAddress(&pWqh, g_Wqh);
    cudaGetSymbolAddress(&pWql, g_Wql);
    cudaGetSymbolAddress(&pWph, g_Wph);
    cudaGetSymbolAddress(&pWpl, g_Wpl);
    cudaGetSymbolAddress(&pQh,  g_QKVh);
    cudaGetSymbolAddress(&pQl,  g_QKVl);
    cudaGetSymbolAddress(&pAh,  g_ATTh);
    cudaGetSymbolAddress(&pAl,  g_ATTl);

    cudaFuncSetAttribute((const void*)gemm_split_kernel<true>,
                         cudaFuncAttributeMaxDynamicSharedMemorySize, 65536);
    cudaFuncSetAttribute((const void*)gemm_split_kernel<false>,
                         cudaFuncAttributeMaxDynamicSharedMemorySize, 65536);
    cudaFuncSetAttribute((const void*)attn_kernel,
                         cudaFuncAttributeMaxDynamicSharedMemorySize, 196608);

    // 1) split inputs to (hi, lo) bf16
    {
        int n4 = (MROWS * CDIM) / 4;  // 16,777,216
        split_kernel<<<n4 / 256, 256>>>((const float4*)x, (uint32_t*)pXh, (uint32_t*)pXl, n4);
    }
    {
        int n4 = (CDIM * N_QKV) / 4;  // 3,145,728
        split_kernel<<<n4 / 256, 256>>>((const float4*)wq, (uint32_t*)pWqh, (uint32_t*)pWql, n4);
    }
    {
        int n4 = (CDIM * CDIM) / 4;   // 1,048,576
        split_kernel<<<n4 / 256, 256>>>((const float4*)wp, (uint32_t*)pWph, (uint32_t*)pWpl, n4);
    }

    // 2) QKV = X @ Wqkv  -> split bf16 output
    {
        dim3 grid(N_QKV / 128, MROWS / 128);  // (48, 256)
        gemm_split_kernel<true><<<grid, 256, 65536>>>(
            (const __nv_bfloat16*)pXh, (const __nv_bfloat16*)pXl,
            (const __nv_bfloat16*)pWqh, (const __nv_bfloat16*)pWql,
            (__nv_bfloat16*)pQh, (__nv_bfloat16*)pQl, nullptr,
            MROWS, N_QKV, CDIM);
    }

    // 3) blocked causal attention -> split bf16 output
    attn_kernel<<<BATCH * NBLK * NHEAD, 256, 196608>>>(
        (const __nv_bfloat16*)pQh, (const __nv_bfloat16*)pQl,
        (__nv_bfloat16*)pAh, (__nv_bfloat16*)pAl);

    // 4) Y = attn @ Wproj -> fp32 final output
    {
        dim3 grid(CDIM / 128, MROWS / 128);  // (16, 256)
        gemm_split_kernel<false><<<grid, 256, 65536>>>(
            (const __nv_bfloat16*)pAh, (const __nv_bfloat16*)pAl,
            (const __nv_bfloat16*)pWph, (const __nv_bfloat16*)pWpl,
            nullptr, nullptr, out,
            MROWS, CDIM, CDIM);
    }
}